// round 2
// baseline (speedup 1.0000x reference)
#include <cuda_runtime.h>
#include <math.h>

#define NN 100000
#define EE 1600000
#define HH 128
#define CC 40
#define BN_EPS 1e-5f

// ---------------- scratch (static device globals; no runtime alloc) ----------------
__device__ float  g_h[(size_t)NN * HH];    // GEMM output (also reused as h3: NN*40)
__device__ float  g_agg[(size_t)NN * HH];  // scatter target / layer output (reused NN*40 in L3)
__device__ double g_stats[2 * HH];         // column sum / sumsq
__device__ float  g_scale[HH];             // BN fused scale
__device__ float  g_shift[HH];             // BN fused shift
__device__ int    g_degcnt[NN];
__device__ float  g_dinv[NN];              // deg^-1/2
__device__ float  g_invdeg[NN];            // deg^-1

// ---------------- helpers ----------------
__device__ __forceinline__ void fma4(float4& a, float s, float4 w) {
    a.x = fmaf(s, w.x, a.x);
    a.y = fmaf(s, w.y, a.y);
    a.z = fmaf(s, w.z, a.z);
    a.w = fmaf(s, w.w, a.w);
}

__device__ __forceinline__ float4 bn_relu4(float4 v, float4 sc, float4 sh) {
    float4 r;
    r.x = fmaxf(fmaf(v.x, sc.x, sh.x), 0.f);
    r.y = fmaxf(fmaf(v.y, sc.y, sh.y), 0.f);
    r.z = fmaxf(fmaf(v.z, sc.z, sh.z), 0.f);
    r.w = fmaxf(fmaf(v.w, sc.w, sh.w), 0.f);
    return r;
}

// ---------------- degree ----------------
__global__ void deg_count_kernel(const int* __restrict__ dst) {
    int e = blockIdx.x * blockDim.x + threadIdx.x;
    if (e < EE) atomicAdd(&g_degcnt[dst[e]], 1);
}

__global__ void deg_finish_kernel() {
    int i = blockIdx.x * blockDim.x + threadIdx.x;
    if (i < NN) {
        float f = (float)(g_degcnt[i] + 1);
        g_dinv[i]   = rsqrtf(f);
        g_invdeg[i] = 1.0f / f;
    }
}

// ---------------- GEMM: [n,128] @ [128,128], optional fused BN+ReLU on input ----------------
// block = 256 threads (8 warps); block tile = 64 rows x 128 cols; each warp: 8 rows.
// dyn smem: W (128x128 f32 = 64KB) + X staging (8 warps * 8 rows * 128 f32 = 32KB) = 96KB
template<bool BN>
__global__ __launch_bounds__(256) void gemm128_kernel(
    const float* __restrict__ X, const float* __restrict__ W,
    float* __restrict__ Y, int nrows)
{
    extern __shared__ float smem[];
    float4* Ws = (float4*)smem;               // [128][32] float4
    float4* Xs = (float4*)smem + HH * 32;     // [8 warps][8 rows][32] float4

    int tid  = threadIdx.x;
    int lane = tid & 31, warp = tid >> 5;

    const float4* W4 = (const float4*)W;
    for (int i = tid; i < HH * 32; i += 256) Ws[i] = W4[i];
    __syncthreads();

    float4 sc, sh;
    if (BN) { sc = ((const float4*)g_scale)[lane]; sh = ((const float4*)g_shift)[lane]; }

    int base = blockIdx.x * 64 + warp * 8;
    const float4* X4 = (const float4*)X;
    float4* Xw = Xs + warp * 8 * 32;

#pragma unroll
    for (int r = 0; r < 8; r++) {
        int row = base + r;
        float4 xv = make_float4(0.f, 0.f, 0.f, 0.f);
        if (row < nrows) xv = X4[(size_t)row * 32 + lane];
        if (BN) xv = bn_relu4(xv, sc, sh);
        Xw[r * 32 + lane] = xv;
    }
    __syncwarp();

    float4 acc[8];
#pragma unroll
    for (int r = 0; r < 8; r++) acc[r] = make_float4(0.f, 0.f, 0.f, 0.f);

#pragma unroll 4
    for (int k0 = 0; k0 < 32; k0++) {
        float4 w0 = Ws[(4 * k0 + 0) * 32 + lane];
        float4 w1 = Ws[(4 * k0 + 1) * 32 + lane];
        float4 w2 = Ws[(4 * k0 + 2) * 32 + lane];
        float4 w3 = Ws[(4 * k0 + 3) * 32 + lane];
#pragma unroll
        for (int r = 0; r < 8; r++) {
            float4 xv = Xw[r * 32 + k0];
            fma4(acc[r], xv.x, w0);
            fma4(acc[r], xv.y, w1);
            fma4(acc[r], xv.z, w2);
            fma4(acc[r], xv.w, w3);
        }
    }

#pragma unroll
    for (int r = 0; r < 8; r++) {
        int row = base + r;
        if (row < nrows) ((float4*)Y)[(size_t)row * 32 + lane] = acc[r];
    }
}

// ---------------- GEMM: [n,128] @ [128,40] with fused BN+ReLU on input ----------------
// lane handles col=lane and (lane<8) col=32+lane. dyn smem: 20KB W + 32KB X = 52KB
template<bool BN>
__global__ __launch_bounds__(256) void gemm40_kernel(
    const float* __restrict__ X, const float* __restrict__ W,
    float* __restrict__ Y, int nrows)
{
    extern __shared__ float smem[];
    float*  Ws = smem;                        // [128][40]
    float4* Xs = (float4*)(smem + HH * CC);   // [8][8][32] float4

    int tid  = threadIdx.x;
    int lane = tid & 31, warp = tid >> 5;

    for (int i = tid; i < HH * CC; i += 256) Ws[i] = W[i];
    __syncthreads();

    float4 sc, sh;
    if (BN) { sc = ((const float4*)g_scale)[lane]; sh = ((const float4*)g_shift)[lane]; }

    int base = blockIdx.x * 64 + warp * 8;
    const float4* X4 = (const float4*)X;
    float4* Xw = Xs + warp * 8 * 32;

#pragma unroll
    for (int r = 0; r < 8; r++) {
        int row = base + r;
        float4 xv = make_float4(0.f, 0.f, 0.f, 0.f);
        if (row < nrows) xv = X4[(size_t)row * 32 + lane];
        if (BN) xv = bn_relu4(xv, sc, sh);
        Xw[r * 32 + lane] = xv;
    }
    __syncwarp();

    float acca[8], accb[8];
#pragma unroll
    for (int r = 0; r < 8; r++) { acca[r] = 0.f; accb[r] = 0.f; }

    bool hasb = (lane < 8);

#pragma unroll 4
    for (int k0 = 0; k0 < 32; k0++) {
        float wa[4], wb[4];
#pragma unroll
        for (int j = 0; j < 4; j++) {
            wa[j] = Ws[(4 * k0 + j) * CC + lane];
            wb[j] = hasb ? Ws[(4 * k0 + j) * CC + 32 + lane] : 0.f;
        }
#pragma unroll
        for (int r = 0; r < 8; r++) {
            float4 xv = Xw[r * 32 + k0];
            acca[r] = fmaf(xv.x, wa[0], acca[r]);
            acca[r] = fmaf(xv.y, wa[1], acca[r]);
            acca[r] = fmaf(xv.z, wa[2], acca[r]);
            acca[r] = fmaf(xv.w, wa[3], acca[r]);
            accb[r] = fmaf(xv.x, wb[0], accb[r]);
            accb[r] = fmaf(xv.y, wb[1], accb[r]);
            accb[r] = fmaf(xv.z, wb[2], accb[r]);
            accb[r] = fmaf(xv.w, wb[3], accb[r]);
        }
    }

#pragma unroll
    for (int r = 0; r < 8; r++) {
        int row = base + r;
        if (row < nrows) {
            Y[(size_t)row * CC + lane] = acca[r];
            if (hasb) Y[(size_t)row * CC + 32 + lane] = accb[r];
        }
    }
}

// ---------------- edge scatter: agg[dst] += dinv[src]*dinv[dst]*h[src] ----------------
// warp per edge (CH4=32): lane q handles float4 chunk q. For CH4=10, thread per chunk.
template<int CH4>
__global__ __launch_bounds__(256) void scatter_kernel(
    const float* __restrict__ h, const int* __restrict__ src,
    const int* __restrict__ dst, float* __restrict__ agg)
{
    unsigned int idx = blockIdx.x * blockDim.x + threadIdx.x;
    unsigned int total = (unsigned int)EE * CH4;
    if (idx >= total) return;
    int e, q;
    if (CH4 == 32) { e = idx >> 5; q = idx & 31; }
    else           { e = idx / CH4; q = idx - e * CH4; }

    int s = __ldg(&src[e]);
    int d = __ldg(&dst[e]);
    float nrm = __ldg(&g_dinv[s]) * __ldg(&g_dinv[d]);
    float4 v = ((const float4*)h)[(size_t)s * CH4 + q];
    float4* outp = (float4*)agg + (size_t)d * CH4 + q;
    asm volatile("red.global.add.v4.f32 [%0], {%1, %2, %3, %4};"
                 :: "l"(outp), "f"(v.x * nrm), "f"(v.y * nrm),
                    "f"(v.z * nrm), "f"(v.w * nrm)
                 : "memory");
}

// ---------------- self-loop + bias + BN stats (fused, one pass over agg) ----------------
// blockDim = 512: thread = (sub 0..3, col 0..127); rows strided by gridDim*4
__global__ __launch_bounds__(512) void finalize_stats_kernel(
    float* __restrict__ agg, const float* __restrict__ h,
    const float* __restrict__ bias)
{
    __shared__ float ssum[4][HH];
    __shared__ float ssq[4][HH];

    int j   = threadIdx.x & (HH - 1);
    int sub = threadIdx.x >> 7;
    float b = bias[j];

    float s = 0.f, s2 = 0.f;
    for (int i = blockIdx.x * 4 + sub; i < NN; i += gridDim.x * 4) {
        float v = agg[(size_t)i * HH + j] + g_invdeg[i] * h[(size_t)i * HH + j] + b;
        agg[(size_t)i * HH + j] = v;
        s += v;
        s2 = fmaf(v, v, s2);
    }
    ssum[sub][j] = s;
    ssq[sub][j]  = s2;
    __syncthreads();
    if (sub == 0) {
        double ts  = (double)ssum[0][j] + ssum[1][j] + ssum[2][j] + ssum[3][j];
        double ts2 = (double)ssq[0][j] + ssq[1][j] + ssq[2][j] + ssq[3][j];
        atomicAdd(&g_stats[j], ts);
        atomicAdd(&g_stats[HH + j], ts2);
    }
}

__global__ void stats_final_kernel(const float* __restrict__ g,
                                   const float* __restrict__ be)
{
    int j = threadIdx.x;
    double mu  = g_stats[j] / (double)NN;
    double var = g_stats[HH + j] / (double)NN - mu * mu;
    float rs = rsqrtf((float)var + BN_EPS);
    float sc = g[j] * rs;
    g_scale[j] = sc;
    g_shift[j] = be[j] - (float)mu * sc;
}

// ---------------- layer-3 epilogue: self-loop + bias + log_softmax, warp per row ----------------
__global__ __launch_bounds__(256) void final_softmax_kernel(
    const float* __restrict__ agg3, const float* __restrict__ h3,
    const float* __restrict__ b3, float* __restrict__ out)
{
    int gw   = (blockIdx.x * blockDim.x + threadIdx.x) >> 5;
    int lane = threadIdx.x & 31;
    if (gw >= NN) return;
    size_t rb = (size_t)gw * CC;
    float id = g_invdeg[gw];

    float v1 = agg3[rb + lane] + id * h3[rb + lane] + b3[lane];
    float v2 = -INFINITY;
    if (lane < 8) v2 = agg3[rb + 32 + lane] + id * h3[rb + 32 + lane] + b3[32 + lane];

    float m = fmaxf(v1, v2);
#pragma unroll
    for (int off = 16; off > 0; off >>= 1)
        m = fmaxf(m, __shfl_xor_sync(0xFFFFFFFFu, m, off));

    float s = expf(v1 - m) + ((lane < 8) ? expf(v2 - m) : 0.f);
#pragma unroll
    for (int off = 16; off > 0; off >>= 1)
        s += __shfl_xor_sync(0xFFFFFFFFu, s, off);

    float l = m + logf(s);
    out[rb + lane] = v1 - l;
    if (lane < 8) out[rb + 32 + lane] = v2 - l;
}

// ---------------- launch ----------------
extern "C" void kernel_launch(void* const* d_in, const int* in_sizes, int n_in,
                              void* d_out, int out_size)
{
    const float* x   = (const float*)d_in[0];
    const float* W1  = (const float*)d_in[1];
    const float* b1  = (const float*)d_in[2];
    const float* W2  = (const float*)d_in[3];
    const float* b2  = (const float*)d_in[4];
    const float* W3  = (const float*)d_in[5];
    const float* b3  = (const float*)d_in[6];
    const float* g1  = (const float*)d_in[7];
    const float* be1 = (const float*)d_in[8];
    const float* g2  = (const float*)d_in[9];
    const float* be2 = (const float*)d_in[10];
    const int*   ei  = (const int*)d_in[11];
    const int* src = ei;
    const int* dst = ei + EE;
    float* out = (float*)d_out;

    void* p;
    cudaGetSymbolAddress(&p, g_h);      float*  h      = (float*)p;
    cudaGetSymbolAddress(&p, g_agg);    float*  agg    = (float*)p;
    cudaGetSymbolAddress(&p, g_stats);  double* stats  = (double*)p;
    cudaGetSymbolAddress(&p, g_degcnt); int*    degcnt = (int*)p;

    const int SMEM128 = (HH * HH + 8 * 8 * HH) * 4;   // 96 KB
    const int SMEM40  = (HH * CC + 8 * 8 * HH) * 4;   // 52 KB
    cudaFuncSetAttribute(gemm128_kernel<false>, cudaFuncAttributeMaxDynamicSharedMemorySize, SMEM128);
    cudaFuncSetAttribute(gemm128_kernel<true>,  cudaFuncAttributeMaxDynamicSharedMemorySize, SMEM128);
    cudaFuncSetAttribute(gemm40_kernel<true>,   cudaFuncAttributeMaxDynamicSharedMemorySize, SMEM40);

    const int GEMM_GRID = (NN + 63) / 64;

    // degrees
    cudaMemsetAsync(degcnt, 0, NN * sizeof(int));
    deg_count_kernel<<<(EE + 255) / 256, 256>>>(dst);
    deg_finish_kernel<<<(NN + 255) / 256, 256>>>();

    // ---- layer 1 ----
    gemm128_kernel<false><<<GEMM_GRID, 256, SMEM128>>>(x, W1, h, NN);
    cudaMemsetAsync(agg, 0, (size_t)NN * HH * sizeof(float));
    scatter_kernel<32><<<(unsigned)EE * 32 / 256, 256>>>(h, src, dst, agg);
    cudaMemsetAsync(stats, 0, 2 * HH * sizeof(double));
    finalize_stats_kernel<<<592, 512>>>(agg, h, b1);
    stats_final_kernel<<<1, HH>>>(g1, be1);

    // ---- layer 2 ----
    gemm128_kernel<true><<<GEMM_GRID, 256, SMEM128>>>(agg, W2, h, NN);
    cudaMemsetAsync(agg, 0, (size_t)NN * HH * sizeof(float));
    scatter_kernel<32><<<(unsigned)EE * 32 / 256, 256>>>(h, src, dst, agg);
    cudaMemsetAsync(stats, 0, 2 * HH * sizeof(double));
    finalize_stats_kernel<<<592, 512>>>(agg, h, b2);
    stats_final_kernel<<<1, HH>>>(g2, be2);

    // ---- layer 3 ----
    gemm40_kernel<true><<<GEMM_GRID, 256, SMEM40>>>(agg, W3, h, NN);
    cudaMemsetAsync(agg, 0, (size_t)NN * CC * sizeof(float));
    scatter_kernel<10><<<(unsigned)EE * 10 / 256, 256>>>(h, src, dst, agg);
    final_softmax_kernel<<<(NN + 7) / 8, 256>>>(agg, h, b3, out);
}

// round 3
// speedup vs baseline: 1.5640x; 1.5640x over previous
#include <cuda_runtime.h>
#include <math.h>

#define NN 100000
#define EE 1600000
#define HH 128
#define CC 40
#define BN_EPS 1e-5f
#define SCAN_BLK 1024
#define SCAN_NB ((NN + SCAN_BLK - 1) / SCAN_BLK)   // 98

// ---------------- scratch (static device globals; no runtime alloc) ----------------
__device__ float  g_h[(size_t)NN * HH];    // GEMM output
__device__ float  g_agg[(size_t)NN * HH];  // aggregation output / next-layer input
__device__ double g_stats[2 * HH];         // column sum / sumsq
__device__ float  g_scale[HH];             // BN fused scale
__device__ float  g_shift[HH];             // BN fused shift
__device__ int    g_degcnt[NN];            // edge-only in-degree
__device__ float  g_dinv[NN];              // (deg+1)^-1/2
__device__ float  g_invdeg[NN];            // (deg+1)^-1
__device__ int    g_rowptr[NN];            // CSR row start (exclusive prefix of degcnt)
__device__ int    g_cursor[NN];
__device__ int    g_blksum[SCAN_NB];
__device__ int2   g_csr[EE];               // {src, bitcast(norm)} sorted by dst

// ---------------- helpers ----------------
__device__ __forceinline__ void fma4(float4& a, float s, float4 w) {
    a.x = fmaf(s, w.x, a.x);
    a.y = fmaf(s, w.y, a.y);
    a.z = fmaf(s, w.z, a.z);
    a.w = fmaf(s, w.w, a.w);
}

__device__ __forceinline__ float4 bn_relu4(float4 v, float4 sc, float4 sh) {
    float4 r;
    r.x = fmaxf(fmaf(v.x, sc.x, sh.x), 0.f);
    r.y = fmaxf(fmaf(v.y, sc.y, sh.y), 0.f);
    r.z = fmaxf(fmaf(v.z, sc.z, sh.z), 0.f);
    r.w = fmaxf(fmaf(v.w, sc.w, sh.w), 0.f);
    return r;
}

// ---------------- degree ----------------
__global__ void deg_count_kernel(const int* __restrict__ dst) {
    int e = blockIdx.x * blockDim.x + threadIdx.x;
    if (e < EE) atomicAdd(&g_degcnt[dst[e]], 1);
}

__global__ void deg_finish_kernel() {
    int i = blockIdx.x * blockDim.x + threadIdx.x;
    if (i < NN) {
        float f = (float)(g_degcnt[i] + 1);
        g_dinv[i]   = rsqrtf(f);
        g_invdeg[i] = 1.0f / f;
    }
}

// ---------------- exclusive scan of degcnt -> rowptr ----------------
__global__ __launch_bounds__(SCAN_BLK) void scan1_kernel() {
    __shared__ int sm[SCAN_BLK];
    int i = blockIdx.x * SCAN_BLK + threadIdx.x;
    int v = (i < NN) ? g_degcnt[i] : 0;
    sm[threadIdx.x] = v;
    __syncthreads();
    for (int off = 1; off < SCAN_BLK; off <<= 1) {
        int t = (threadIdx.x >= off) ? sm[threadIdx.x - off] : 0;
        __syncthreads();
        sm[threadIdx.x] += t;
        __syncthreads();
    }
    if (i < NN) g_rowptr[i] = sm[threadIdx.x] - v;   // exclusive
    if (threadIdx.x == SCAN_BLK - 1) g_blksum[blockIdx.x] = sm[SCAN_BLK - 1];
}

__global__ void scan2_kernel() {   // 1 block, 128 threads, SCAN_NB<=128
    __shared__ int sm[128];
    int v = (threadIdx.x < SCAN_NB) ? g_blksum[threadIdx.x] : 0;
    sm[threadIdx.x] = v;
    __syncthreads();
    for (int off = 1; off < 128; off <<= 1) {
        int t = (threadIdx.x >= off) ? sm[threadIdx.x - off] : 0;
        __syncthreads();
        sm[threadIdx.x] += t;
        __syncthreads();
    }
    if (threadIdx.x < SCAN_NB) g_blksum[threadIdx.x] = sm[threadIdx.x] - v;
}

__global__ void scan3_kernel() {
    int i = blockIdx.x * blockDim.x + threadIdx.x;
    if (i < NN) g_rowptr[i] += g_blksum[i >> 10];
}

// ---------------- CSR fill ----------------
__global__ void csr_fill_kernel(const int* __restrict__ src,
                                const int* __restrict__ dst) {
    int e = blockIdx.x * blockDim.x + threadIdx.x;
    if (e >= EE) return;
    int s = src[e], d = dst[e];
    int pos = g_rowptr[d] + atomicAdd(&g_cursor[d], 1);
    float w = g_dinv[s] * g_dinv[d];
    g_csr[pos] = make_int2(s, __float_as_int(w));
}

// ---------------- GEMM: [n,128] @ [128,128], optional fused BN+ReLU on input ----------------
template<bool BN>
__global__ __launch_bounds__(256) void gemm128_kernel(
    const float* __restrict__ X, const float* __restrict__ W,
    float* __restrict__ Y, int nrows)
{
    extern __shared__ float smem[];
    float4* Ws = (float4*)smem;               // [128][32] float4
    float4* Xs = (float4*)smem + HH * 32;     // [8 warps][8 rows][32] float4

    int tid  = threadIdx.x;
    int lane = tid & 31, warp = tid >> 5;

    const float4* W4 = (const float4*)W;
    for (int i = tid; i < HH * 32; i += 256) Ws[i] = W4[i];
    __syncthreads();

    float4 sc, sh;
    if (BN) { sc = ((const float4*)g_scale)[lane]; sh = ((const float4*)g_shift)[lane]; }

    int base = blockIdx.x * 64 + warp * 8;
    const float4* X4 = (const float4*)X;
    float4* Xw = Xs + warp * 8 * 32;

#pragma unroll
    for (int r = 0; r < 8; r++) {
        int row = base + r;
        float4 xv = make_float4(0.f, 0.f, 0.f, 0.f);
        if (row < nrows) xv = X4[(size_t)row * 32 + lane];
        if (BN) xv = bn_relu4(xv, sc, sh);
        Xw[r * 32 + lane] = xv;
    }
    __syncwarp();

    float4 acc[8];
#pragma unroll
    for (int r = 0; r < 8; r++) acc[r] = make_float4(0.f, 0.f, 0.f, 0.f);

#pragma unroll 4
    for (int k0 = 0; k0 < 32; k0++) {
        float4 w0 = Ws[(4 * k0 + 0) * 32 + lane];
        float4 w1 = Ws[(4 * k0 + 1) * 32 + lane];
        float4 w2 = Ws[(4 * k0 + 2) * 32 + lane];
        float4 w3 = Ws[(4 * k0 + 3) * 32 + lane];
#pragma unroll
        for (int r = 0; r < 8; r++) {
            float4 xv = Xw[r * 32 + k0];
            fma4(acc[r], xv.x, w0);
            fma4(acc[r], xv.y, w1);
            fma4(acc[r], xv.z, w2);
            fma4(acc[r], xv.w, w3);
        }
    }

#pragma unroll
    for (int r = 0; r < 8; r++) {
        int row = base + r;
        if (row < nrows) ((float4*)Y)[(size_t)row * 32 + lane] = acc[r];
    }
}

// ---------------- GEMM: [n,128] @ [128,40] with fused BN+ReLU on input ----------------
template<bool BN>
__global__ __launch_bounds__(256) void gemm40_kernel(
    const float* __restrict__ X, const float* __restrict__ W,
    float* __restrict__ Y, int nrows)
{
    extern __shared__ float smem[];
    float*  Ws = smem;                        // [128][40]
    float4* Xs = (float4*)(smem + HH * CC);   // [8][8][32] float4

    int tid  = threadIdx.x;
    int lane = tid & 31, warp = tid >> 5;

    for (int i = tid; i < HH * CC; i += 256) Ws[i] = W[i];
    __syncthreads();

    float4 sc, sh;
    if (BN) { sc = ((const float4*)g_scale)[lane]; sh = ((const float4*)g_shift)[lane]; }

    int base = blockIdx.x * 64 + warp * 8;
    const float4* X4 = (const float4*)X;
    float4* Xw = Xs + warp * 8 * 32;

#pragma unroll
    for (int r = 0; r < 8; r++) {
        int row = base + r;
        float4 xv = make_float4(0.f, 0.f, 0.f, 0.f);
        if (row < nrows) xv = X4[(size_t)row * 32 + lane];
        if (BN) xv = bn_relu4(xv, sc, sh);
        Xw[r * 32 + lane] = xv;
    }
    __syncwarp();

    float acca[8], accb[8];
#pragma unroll
    for (int r = 0; r < 8; r++) { acca[r] = 0.f; accb[r] = 0.f; }

    bool hasb = (lane < 8);

#pragma unroll 4
    for (int k0 = 0; k0 < 32; k0++) {
        float wa[4], wb[4];
#pragma unroll
        for (int j = 0; j < 4; j++) {
            wa[j] = Ws[(4 * k0 + j) * CC + lane];
            wb[j] = hasb ? Ws[(4 * k0 + j) * CC + 32 + lane] : 0.f;
        }
#pragma unroll
        for (int r = 0; r < 8; r++) {
            float4 xv = Xw[r * 32 + k0];
            acca[r] = fmaf(xv.x, wa[0], acca[r]);
            acca[r] = fmaf(xv.y, wa[1], acca[r]);
            acca[r] = fmaf(xv.z, wa[2], acca[r]);
            acca[r] = fmaf(xv.w, wa[3], acca[r]);
            accb[r] = fmaf(xv.x, wb[0], accb[r]);
            accb[r] = fmaf(xv.y, wb[1], accb[r]);
            accb[r] = fmaf(xv.z, wb[2], accb[r]);
            accb[r] = fmaf(xv.w, wb[3], accb[r]);
        }
    }

#pragma unroll
    for (int r = 0; r < 8; r++) {
        int row = base + r;
        if (row < nrows) {
            Y[(size_t)row * CC + lane] = acca[r];
            if (hasb) Y[(size_t)row * CC + 32 + lane] = accb[r];
        }
    }
}

// ---------------- fused CSR aggregation + self-loop + bias + BN stats (H=128) ----------------
// warp per node (grid-stride); lane q owns float4 chunk q of the row.
__global__ __launch_bounds__(256) void aggregate128_kernel(
    const float* __restrict__ h, float* __restrict__ agg,
    const float* __restrict__ bias)
{
    __shared__ float ssum[8 * HH];
    __shared__ float ssq[8 * HH];

    int lane = threadIdx.x & 31, warp = threadIdx.x >> 5;
    int gw = blockIdx.x * 8 + warp;
    int nwarps = gridDim.x * 8;

    float4 bb = ((const float4*)bias)[lane];
    float4 ps  = make_float4(0.f, 0.f, 0.f, 0.f);
    float4 ps2 = make_float4(0.f, 0.f, 0.f, 0.f);

    const float4* h4 = (const float4*)h;

    for (int i = gw; i < NN; i += nwarps) {
        int start = g_rowptr[i];
        int end   = start + g_degcnt[i];
        float4 acc = make_float4(0.f, 0.f, 0.f, 0.f);

        int k = start;
        for (; k + 1 < end; k += 2) {
            int2 p0 = g_csr[k];
            int2 p1 = g_csr[k + 1];
            float4 v0 = __ldg(h4 + (size_t)p0.x * 32 + lane);
            float4 v1 = __ldg(h4 + (size_t)p1.x * 32 + lane);
            fma4(acc, __int_as_float(p0.y), v0);
            fma4(acc, __int_as_float(p1.y), v1);
        }
        if (k < end) {
            int2 p0 = g_csr[k];
            float4 v0 = __ldg(h4 + (size_t)p0.x * 32 + lane);
            fma4(acc, __int_as_float(p0.y), v0);
        }

        float4 hv = h4[(size_t)i * 32 + lane];
        float id = g_invdeg[i];
        acc.x = fmaf(id, hv.x, acc.x) + bb.x;
        acc.y = fmaf(id, hv.y, acc.y) + bb.y;
        acc.z = fmaf(id, hv.z, acc.z) + bb.z;
        acc.w = fmaf(id, hv.w, acc.w) + bb.w;
        ((float4*)agg)[(size_t)i * 32 + lane] = acc;

        ps.x += acc.x; ps.y += acc.y; ps.z += acc.z; ps.w += acc.w;
        ps2.x = fmaf(acc.x, acc.x, ps2.x);
        ps2.y = fmaf(acc.y, acc.y, ps2.y);
        ps2.z = fmaf(acc.z, acc.z, ps2.z);
        ps2.w = fmaf(acc.w, acc.w, ps2.w);
    }

    ((float4*)(ssum + warp * HH))[lane] = ps;
    ((float4*)(ssq  + warp * HH))[lane] = ps2;
    __syncthreads();
    if (threadIdx.x < HH) {
        int j = threadIdx.x;
        float ts = 0.f, ts2 = 0.f;
#pragma unroll
        for (int w = 0; w < 8; w++) {
            ts  += ssum[w * HH + j];
            ts2 += ssq[w * HH + j];
        }
        atomicAdd(&g_stats[j],      (double)ts);
        atomicAdd(&g_stats[HH + j], (double)ts2);
    }
}

__global__ void stats_final_kernel(const float* __restrict__ g,
                                   const float* __restrict__ be)
{
    int j = threadIdx.x;
    double mu  = g_stats[j] / (double)NN;
    double var = g_stats[HH + j] / (double)NN - mu * mu;
    float rs = rsqrtf((float)var + BN_EPS);
    float sc = g[j] * rs;
    g_scale[j] = sc;
    g_shift[j] = be[j] - (float)mu * sc;
}

// ---------------- layer-3: fused CSR aggregation + self-loop + bias + log_softmax ----------------
// warp per node; lane covers col=lane (all) and col=32+lane (lane<8)
__global__ __launch_bounds__(256) void aggregate40_softmax_kernel(
    const float* __restrict__ h3, const float* __restrict__ b3,
    float* __restrict__ out)
{
    int lane = threadIdx.x & 31, warp = threadIdx.x >> 5;
    int gw = blockIdx.x * 8 + warp;
    if (gw >= NN) return;

    int start = g_rowptr[gw];
    int end   = start + g_degcnt[gw];
    bool hi = (lane < 8);

    float a1 = 0.f, a2 = 0.f;
    for (int k = start; k < end; k++) {
        int2 p = g_csr[k];
        float w = __int_as_float(p.y);
        size_t rb = (size_t)p.x * CC;
        a1 = fmaf(w, __ldg(&h3[rb + lane]), a1);
        if (hi) a2 = fmaf(w, __ldg(&h3[rb + 32 + lane]), a2);
    }

    size_t rb = (size_t)gw * CC;
    float id = g_invdeg[gw];
    float v1 = fmaf(id, h3[rb + lane], a1) + b3[lane];
    float v2 = -INFINITY;
    if (hi) v2 = fmaf(id, h3[rb + 32 + lane], a2) + b3[32 + lane];

    float m = fmaxf(v1, v2);
#pragma unroll
    for (int off = 16; off > 0; off >>= 1)
        m = fmaxf(m, __shfl_xor_sync(0xFFFFFFFFu, m, off));

    float s = expf(v1 - m) + (hi ? expf(v2 - m) : 0.f);
#pragma unroll
    for (int off = 16; off > 0; off >>= 1)
        s += __shfl_xor_sync(0xFFFFFFFFu, s, off);

    float l = m + logf(s);
    out[rb + lane] = v1 - l;
    if (hi) out[rb + 32 + lane] = v2 - l;
}

// ---------------- launch ----------------
extern "C" void kernel_launch(void* const* d_in, const int* in_sizes, int n_in,
                              void* d_out, int out_size)
{
    const float* x   = (const float*)d_in[0];
    const float* W1  = (const float*)d_in[1];
    const float* b1  = (const float*)d_in[2];
    const float* W2  = (const float*)d_in[3];
    const float* b2  = (const float*)d_in[4];
    const float* W3  = (const float*)d_in[5];
    const float* b3  = (const float*)d_in[6];
    const float* g1  = (const float*)d_in[7];
    const float* be1 = (const float*)d_in[8];
    const float* g2  = (const float*)d_in[9];
    const float* be2 = (const float*)d_in[10];
    const int*   ei  = (const int*)d_in[11];
    const int* src = ei;
    const int* dst = ei + EE;
    float* out = (float*)d_out;

    void* p;
    cudaGetSymbolAddress(&p, g_h);      float*  h      = (float*)p;
    cudaGetSymbolAddress(&p, g_agg);    float*  agg    = (float*)p;
    cudaGetSymbolAddress(&p, g_stats);  double* stats  = (double*)p;
    cudaGetSymbolAddress(&p, g_degcnt); int*    degcnt = (int*)p;
    cudaGetSymbolAddress(&p, g_cursor); int*    cursor = (int*)p;

    const int SMEM128 = (HH * HH + 8 * 8 * HH) * 4;   // 96 KB
    const int SMEM40  = (HH * CC + 8 * 8 * HH) * 4;   // 52 KB
    cudaFuncSetAttribute(gemm128_kernel<false>, cudaFuncAttributeMaxDynamicSharedMemorySize, SMEM128);
    cudaFuncSetAttribute(gemm128_kernel<true>,  cudaFuncAttributeMaxDynamicSharedMemorySize, SMEM128);
    cudaFuncSetAttribute(gemm40_kernel<true>,   cudaFuncAttributeMaxDynamicSharedMemorySize, SMEM40);

    const int GEMM_GRID = (NN + 63) / 64;
    const int AGG_GRID  = 1184;   // 8 blocks/SM, warp-per-node grid-stride

    // ---- degree + CSR build (once) ----
    cudaMemsetAsync(degcnt, 0, NN * sizeof(int));
    deg_count_kernel<<<(EE + 255) / 256, 256>>>(dst);
    deg_finish_kernel<<<(NN + 255) / 256, 256>>>();
    scan1_kernel<<<SCAN_NB, SCAN_BLK>>>();
    scan2_kernel<<<1, 128>>>();
    scan3_kernel<<<(NN + 255) / 256, 256>>>();
    cudaMemsetAsync(cursor, 0, NN * sizeof(int));
    csr_fill_kernel<<<(EE + 255) / 256, 256>>>(src, dst);

    // ---- layer 1 ----
    gemm128_kernel<false><<<GEMM_GRID, 256, SMEM128>>>(x, W1, h, NN);
    cudaMemsetAsync(stats, 0, 2 * HH * sizeof(double));
    aggregate128_kernel<<<AGG_GRID, 256>>>(h, agg, b1);
    stats_final_kernel<<<1, HH>>>(g1, be1);

    // ---- layer 2 ----
    gemm128_kernel<true><<<GEMM_GRID, 256, SMEM128>>>(agg, W2, h, NN);
    cudaMemsetAsync(stats, 0, 2 * HH * sizeof(double));
    aggregate128_kernel<<<AGG_GRID, 256>>>(h, agg, b2);
    stats_final_kernel<<<1, HH>>>(g2, be2);

    // ---- layer 3 ----
    gemm40_kernel<true><<<GEMM_GRID, 256, SMEM40>>>(agg, W3, h, NN);
    aggregate40_softmax_kernel<<<(NN + 7) / 8, 256>>>(h, b3, out);
}